// round 1
// baseline (speedup 1.0000x reference)
#include <cuda_runtime.h>

// CapsuleLayer dynamic routing, fully fused into 3 streaming passes + 3 tiny
// squash kernels. Key identity: b_ij after r rounds = u_hat · (v_0+...+v_{r-1}),
// so u_hat never needs to be materialized; it is recomputed per pass from W
// (75.5 MB) instead of storing/re-reading 302 MB.

#define BB 32      // batch
#define JJ 32      // output capsules
#define II 4608    // input capsules
#define DA 8       // d_in
#define DD 16      // d_out
#define CHUNK 32   // i per CTA
#define NCHUNK 144 // 144*32 = 4608
#define CAP_EPS 1e-7f

// scratch (no allocations allowed)
__device__ float g_partial[NCHUNK * BB * JJ * DD]; // per-chunk partial s  (9.4 MB)
__device__ float g_vsum[BB * JJ * DD];             // v0, then v0+v1

// ---------------------------------------------------------------------------
// Pass kernel: grid = NCHUNK CTAs (one 32-i chunk each, all 32 batches),
// block = 512 threads = 16 warps. lane = j (0..31), warp w handles b = 2w,2w+1.
// Shared (dynamic, 49152 B):
//   [0,4096)    W tile buf0   (j*128 + ((8d+a) ^ (j&31)))  XOR-swizzled
//   [4096,8192) W tile buf1
//   [8192,12288) inputs half-chunk: [b][il&15][a] = b*128 + ih*8 + a
// ---------------------------------------------------------------------------
template <int PASS>
__global__ void __launch_bounds__(512, 1)
pass_kernel(const float* __restrict__ xg, const float* __restrict__ Wg) {
    extern __shared__ float sh[];
    float* xsh = sh + 8192;

    const int t    = threadIdx.x;
    const int j    = t & 31;       // lane = output capsule
    const int w    = t >> 5;       // warp id
    const int jlo  = j & 7;
    const int jmid = j & 24;
    const int b0   = 2 * w;
    const int b1   = b0 + 1;
    const int i0   = blockIdx.x * CHUNK;
    const int trow = t >> 7;       // 0..3 (W copy row group)
    const int tda  = t & 127;      // W copy column

    // v history in registers (tiny, L2-hot)
    float v0r[DD], v1r[DD];
    if (PASS > 0) {
#pragma unroll
        for (int d = 0; d < DD; d++) {
            v0r[d] = g_vsum[(b0 * JJ + j) * DD + d];
            v1r[d] = g_vsum[(b1 * JJ + j) * DD + d];
        }
    }

    // inputs, first half of chunk (i0 .. i0+15): contiguous per b in global
    for (int idx = t; idx < 4096; idx += 512) {
        int b = idx >> 7;
        xsh[idx] = xg[b * (II * DA) + i0 * DA + (idx & 127)];
    }

    // W tile prefetch pipeline. Tile for capsule-row jr, position i is the
    // 128 contiguous floats Wg[(jr*II + i)*128 + da]. Swizzled store:
    // phys = jr*128 + (da ^ (jr & 31))  -> conflict-free store AND read.
    float wreg[8];
#pragma unroll
    for (int k = 0; k < 8; k++) {
        int jr = k * 4 + trow;
        wreg[k] = Wg[(jr * II + i0) * 128 + tda];
    }
#pragma unroll
    for (int k = 0; k < 8; k++) {
        int jr = k * 4 + trow;
        sh[jr * 128 + (tda ^ (jr & 31))] = wreg[k];  // buf0
    }
#pragma unroll
    for (int k = 0; k < 8; k++) {
        int jr = k * 4 + trow;
        wreg[k] = Wg[(jr * II + (i0 + 1)) * 128 + tda];
    }
    __syncthreads();

    float acc0[DD], acc1[DD];
#pragma unroll
    for (int d = 0; d < DD; d++) { acc0[d] = 0.f; acc1[d] = 0.f; }

    for (int il = 0; il < CHUNK; ++il) {
        if (il == 16) {  // second half of inputs (readers of half 0 all past last sync)
            for (int idx = t; idx < 4096; idx += 512) {
                int b = idx >> 7;
                xsh[idx] = xg[b * (II * DA) + i0 * DA + 128 + (idx & 127)];
            }
            __syncthreads();
        }

        const float* wb = sh + ((il & 1) << 12) + j * 128;

        // u_hat[b, j(=lane), i0+il, :] for both b's; W value reused across b.
        float u0[DD], u1[DD];
#pragma unroll
        for (int d = 0; d < DD; d++) { u0[d] = 0.f; u1[d] = 0.f; }
#pragma unroll
        for (int a = 0; a < DA; a++) {
            float x0 = xsh[b0 * 128 + (il & 15) * 8 + a];  // broadcast LDS
            float x1 = xsh[b1 * 128 + (il & 15) * 8 + a];
            const int ax = a ^ jlo;
#pragma unroll
            for (int d = 0; d < DD; d++) {
                float wv = wb[((d * 8) ^ jmid) + ax];      // conflict-free LDS
                u0[d] = fmaf(wv, x0, u0[d]);
                u1[d] = fmaf(wv, x1, u1[d]);
            }
        }

        if (PASS == 0) {
            // c = softmax(0) = 1/32 uniform; scale folded into squash round 0.
#pragma unroll
            for (int d = 0; d < DD; d++) { acc0[d] += u0[d]; acc1[d] += u1[d]; }
        } else {
            float l0 = 0.f, l1 = 0.f;
#pragma unroll
            for (int d = 0; d < DD; d++) {
                l0 = fmaf(u0[d], v0r[d], l0);
                l1 = fmaf(u1[d], v1r[d], l1);
            }
            // softmax over j = pure intra-warp butterfly (lanes are all 32 j's)
            float m0 = l0, m1 = l1;
#pragma unroll
            for (int off = 16; off > 0; off >>= 1) {
                m0 = fmaxf(m0, __shfl_xor_sync(0xffffffffu, m0, off));
                m1 = fmaxf(m1, __shfl_xor_sync(0xffffffffu, m1, off));
            }
            float e0 = __expf(l0 - m0), e1 = __expf(l1 - m1);
            float z0 = e0, z1 = e1;
#pragma unroll
            for (int off = 16; off > 0; off >>= 1) {
                z0 += __shfl_xor_sync(0xffffffffu, z0, off);
                z1 += __shfl_xor_sync(0xffffffffu, z1, off);
            }
            float c0 = __fdividef(e0, z0), c1 = __fdividef(e1, z1);
#pragma unroll
            for (int d = 0; d < DD; d++) {
                acc0[d] = fmaf(c0, u0[d], acc0[d]);
                acc1[d] = fmaf(c1, u1[d], acc1[d]);
            }
        }

        // stage next W tile (writes the buffer last READ in iter il-1 -> safe)
        if (il + 1 < CHUNK) {
            float* dst = sh + (((il + 1) & 1) << 12);
#pragma unroll
            for (int k = 0; k < 8; k++) {
                int jr = k * 4 + trow;
                dst[jr * 128 + (tda ^ (jr & 31))] = wreg[k];
            }
            if (il + 2 < CHUNK) {
#pragma unroll
                for (int k = 0; k < 8; k++) {
                    int jr = k * 4 + trow;
                    wreg[k] = Wg[(jr * II + (i0 + il + 2)) * 128 + tda];
                }
            }
            __syncthreads();
        }
    }

    // deterministic two-stage reduction: per-chunk partials, reduced in squash
    float* p0 = &g_partial[((blockIdx.x * BB + b0) * JJ + j) * DD];
    float* p1 = &g_partial[((blockIdx.x * BB + b1) * JJ + j) * DD];
#pragma unroll
    for (int d = 0; d < DD; d++) { p0[d] = acc0[d]; p1[d] = acc1[d]; }
}

// ---------------------------------------------------------------------------
// Squash: one thread per (b,j,d) output element. Sums NCHUNK partials with
// 4-way ILP (L2-resident), then 16-lane shfl reduction for |s|^2.
// ---------------------------------------------------------------------------
template <int ROUND>
__global__ void __launch_bounds__(256)
squash_kernel(float* __restrict__ out) {
    int tid = blockIdx.x * 256 + threadIdx.x;  // = (b*JJ + j)*DD + d
    const float* p = g_partial + tid;
    float s0 = 0.f, s1 = 0.f, s2 = 0.f, s3 = 0.f;
#pragma unroll 4
    for (int c = 0; c < NCHUNK; c += 4) {
        s0 += p[(c + 0) * (BB * JJ * DD)];
        s1 += p[(c + 1) * (BB * JJ * DD)];
        s2 += p[(c + 2) * (BB * JJ * DD)];
        s3 += p[(c + 3) * (BB * JJ * DD)];
    }
    float s = (s0 + s1) + (s2 + s3);
    if (ROUND == 0) s *= 0.03125f;  // uniform c = 1/32 folded here

    float sq = s * s;  // lanes d=0..15 form aligned 16-groups within the warp
#pragma unroll
    for (int off = 8; off > 0; off >>= 1)
        sq += __shfl_xor_sync(0xffffffffu, sq, off);

    float v = s * (sq / ((1.0f + sq) * sqrtf(sq + CAP_EPS)));

    if (ROUND == 0)      g_vsum[tid] = v;        // v0
    else if (ROUND == 1) g_vsum[tid] += v;       // v0 + v1
    else                 out[tid] = v;           // final v2 -> d_out
}

// ---------------------------------------------------------------------------
extern "C" void kernel_launch(void* const* d_in, const int* in_sizes, int n_in,
                              void* d_out, int out_size) {
    (void)in_sizes; (void)n_in; (void)out_size;
    const float* xg = (const float*)d_in[0];   // inputs [32,4608,8]
    const float* Wg = (const float*)d_in[1];   // W      [32,4608,16,8]
    float* out = (float*)d_out;                // [32,32,16]

    const int SMEM = 49152;  // 48 KB: within default dynamic limit, no attribute needed

    pass_kernel<0><<<NCHUNK, 512, SMEM>>>(xg, Wg);
    squash_kernel<0><<<64, 256>>>(out);
    pass_kernel<1><<<NCHUNK, 512, SMEM>>>(xg, Wg);
    squash_kernel<1><<<64, 256>>>(out);
    pass_kernel<2><<<NCHUNK, 512, SMEM>>>(xg, Wg);
    squash_kernel<2><<<64, 256>>>(out);
}